// round 17
// baseline (speedup 1.0000x reference)
#include <cuda_runtime.h>
#include <math.h>

#define BB   16
#define NN   4096
#define EE   65536
#define HH   512
#define MM1  1024
#define MM2  32768

// ---- device scratch. NEVER named in host code (host shadows + ATS would
// silently write host memory and trip the harness mem guard). ---------------
// g_deg starts zero (BSS); kernel #6 re-zeros it for the next iteration.
__device__ int   g_deg[NN];
__device__ int   g_off[NN + 1];
__device__ int   g_cur[NN];
__device__ int   g_src[EE];
__device__ float g_hA [(size_t)BB * NN * 32];
__device__ float g_hB [(size_t)BB * NN * 32];
__device__ float g_w  [(size_t)BB * EE];        // edge softmax weights
__device__ float g_as0[(size_t)BB * NN], g_ad0[(size_t)BB * NN];
__device__ float g_as1[(size_t)BB * NN], g_ad1[(size_t)BB * NN];
__device__ float g_gi [(size_t)BB * 3 * HH];
__device__ float g_gh [(size_t)BB * 3 * HH];
__device__ float g_nh [(size_t)BB * HH];
__device__ float g_o1 [(size_t)BB * MM1];
__device__ float g_o2 [(size_t)BB * MM2];

__device__ __forceinline__ float lrelu(float v) { return v >= 0.f ? v : 0.2f * v; }

// ---- warp rowgemm: C[b][row] = A[b]·W[row] + bias -------------------------
__device__ __forceinline__ void rowgemm_warp(
    const float* __restrict__ A, const float* __restrict__ W,
    const float* __restrict__ bias,
    const float* pr, const float* bg, const float* bb, bool epi,
    float* __restrict__ C, int row, int M, int K, int lane) {
    float acc[16];
#pragma unroll
    for (int b2 = 0; b2 < 16; b2++) acc[b2] = 0.f;
    const float* w = W + (size_t)row * K;
    for (int k = lane * 4; k < K; k += 128) {
        float4 wv = *(const float4*)(w + k);
#pragma unroll
        for (int b2 = 0; b2 < 16; b2++) {
            float4 av = __ldg((const float4*)(A + (size_t)b2 * K + k));
            acc[b2] += wv.x * av.x + wv.y * av.y + wv.z * av.z + wv.w * av.w;
        }
    }
#pragma unroll
    for (int b2 = 0; b2 < 16; b2++) {
#pragma unroll
        for (int o = 16; o > 0; o >>= 1) acc[b2] += __shfl_xor_sync(0xffffffffu, acc[b2], o);
    }
    if (lane == 0) {
        const float inv = rsqrtf(1.f + 1e-5f);
#pragma unroll
        for (int b2 = 0; b2 < 16; b2++) {
            float t = acc[b2] + bias[row];
            if (epi) {
                t = t >= 0.f ? t : pr[row] * t;
                t = t * inv * bg[row] + bb[row];
            }
            C[(size_t)b2 * M + row] = t;
        }
    }
}

// ============ #1: hist + gi + gh + feat3 (all independent) ================
// blocks 0..191: gi; 192..383: gh; 384..639: hist; 640..8831: feat3.
__global__ void k_one(const int* __restrict__ ei,
                      const float* __restrict__ x, const float* __restrict__ hidden,
                      const float* __restrict__ w_ih, const float* __restrict__ b_ih,
                      const float* __restrict__ w_hh, const float* __restrict__ b_hh,
                      const float* __restrict__ svp, const float* __restrict__ W0,
                      const float* __restrict__ a0s, const float* __restrict__ a0d) {
    int blk = blockIdx.x;
    int wid = threadIdx.x >> 5, lane = threadIdx.x & 31;
    if (blk < 192) {
        int row = blk * 8 + wid;
        rowgemm_warp(x, w_ih, b_ih, 0, 0, 0, false, g_gi, row, 3 * HH, 256, lane);
    } else if (blk < 384) {
        int row = (blk - 192) * 8 + wid;
        rowgemm_warp(hidden, w_hh, b_hh, 0, 0, 0, false, g_gh, row, 3 * HH, HH, lane);
    } else if (blk < 640) {
        int i = (blk - 384) * 256 + threadIdx.x;
        if (i < EE) atomicAdd(&g_deg[ei[EE + i]], 1);
    } else {
        int gw = (blk - 640) * 8 + wid;
        if (gw >= BB * NN) return;
        const float* xv = svp + (size_t)gw * 3;
        float v0 = xv[0], v1 = xv[1], v2 = xv[2];
        float hv = W0[lane * 3] * v0 + W0[lane * 3 + 1] * v1 + W0[lane * 3 + 2] * v2;
        g_hA[(size_t)gw * 32 + lane] = hv;
        float ps = hv * a0s[lane];
        float pd = hv * a0d[lane];
#pragma unroll
        for (int o = 16; o > 0; o >>= 1) {
            ps += __shfl_xor_sync(0xffffffffu, ps, o);
            pd += __shfl_xor_sync(0xffffffffu, pd, o);
        }
        if (lane == 0) { g_as0[gw] = ps; g_ad0[gw] = pd; }
    }
}

// ============ #2: scan + GRU combine =======================================
__global__ void k_two(const float* __restrict__ hidden,
                      float* __restrict__ out, int write_nh) {
    int blk = blockIdx.x;
    int tid = threadIdx.x;
    if (blk == 0) {
        __shared__ int s_scan[256];
        int base = tid * 16;
        int v[16]; int sum = 0;
#pragma unroll
        for (int i = 0; i < 16; i++) { v[i] = g_deg[base + i]; sum += v[i]; }
        s_scan[tid] = sum;
        __syncthreads();
        for (int o = 1; o < 256; o <<= 1) {
            int t2 = (tid >= o) ? s_scan[tid - o] : 0;
            __syncthreads();
            s_scan[tid] += t2;
            __syncthreads();
        }
        int run = s_scan[tid] - sum;
#pragma unroll
        for (int i = 0; i < 16; i++) {
            g_off[base + i] = run; g_cur[base + i] = run; run += v[i];
        }
        if (tid == 255) g_off[NN] = run;
    } else {
        int t = (blk - 1) * 256 + tid;
        if (t >= BB * HH) return;
        int b = t / HH, j = t % HH;
        size_t base = (size_t)b * 3 * HH;
        float ir = g_gi[base + j], iz = g_gi[base + HH + j], in_ = g_gi[base + 2 * HH + j];
        float hr = g_gh[base + j], hz = g_gh[base + HH + j], hn = g_gh[base + 2 * HH + j];
        float r = 1.f / (1.f + expf(-(ir + hr)));
        float z = 1.f / (1.f + expf(-(iz + hz)));
        float n = tanhf(in_ + r * hn);
        float hp = hidden[(size_t)b * HH + j];
        float nh = (1.f - z) * n + z * hp;
        g_nh[(size_t)b * HH + j] = nh;
        if (write_nh) out[(size_t)BB * NN * 3 + (size_t)b * HH + j] = nh;
    }
}

// ============ #3: scatter + lin1 ===========================================
// blocks 0..255: scatter; 256..383: lin1 rows.
__global__ void k_three(const int* __restrict__ ei,
                        const float* __restrict__ l1w, const float* __restrict__ l1b,
                        const float* __restrict__ pr1, const float* __restrict__ bg1,
                        const float* __restrict__ bb1) {
    int blk = blockIdx.x;
    int wid = threadIdx.x >> 5, lane = threadIdx.x & 31;
    if (blk < 256) {
        int i = blk * 256 + threadIdx.x;
        if (i < EE) {
            int d = ei[EE + i];
            int pos = atomicAdd(&g_cur[d], 1);
            g_src[pos] = ei[i];
        }
    } else {
        int row = (blk - 256) * 8 + wid;
        rowgemm_warp(g_nh, l1w, l1b, pr1, bg1, bb1, true, g_o1, row, MM1, HH, lane);
    }
}

// ---- single-pass GAT aggregate, no inner-loop shfls -----------------------
template <int LAYER>
__device__ __forceinline__ float gat_aggregate(int gw, int lane, int b, int d) {
    const float* asv = (LAYER == 0) ? g_as0 : g_as1;
    const float* adv = (LAYER == 0) ? g_ad0 : g_ad1;
    const float* hsrc = (LAYER == 0) ? g_hA : g_hB;
    const float* asb = asv + (size_t)b * NN;
    const float* hb = hsrc + (size_t)b * NN * 32;
    float add = adv[gw];
    int beg = g_off[d], end = g_off[d + 1];
    float* wb = g_w + (size_t)b * EE;

    float wsum = 0.f;
    for (int i = beg + lane; i < end; i += 32) {
        float w = expf(lrelu(asb[g_src[i]] + add));
        wb[i] = w;
        wsum += w;
    }
#pragma unroll
    for (int o = 16; o > 0; o >>= 1) wsum += __shfl_xor_sync(0xffffffffu, wsum, o);
    float wself = expf(lrelu(asb[d] + add));
    wsum += wself;
    __syncwarp();

    float acc = wself * hb[(size_t)d * 32 + lane];
#pragma unroll 4
    for (int j = beg; j < end; j++) {
        float w = wb[j];
        int   s = g_src[j];
        acc += w * hb[(size_t)s * 32 + lane];
    }
    return acc / wsum;
}

// ============ #4: agg0 + layer-1 transform  <-- PROFILED SLOT ==============
__global__ void k_agg0_feat1(const float* __restrict__ b0,
                             const float* __restrict__ W1,
                             const float* __restrict__ a1s,
                             const float* __restrict__ a1d,
                             int nwork) {
    int gw = (blockIdx.x * blockDim.x + threadIdx.x) >> 5;
    int lane = threadIdx.x & 31;
    if (gw >= nwork) return;
    int b = gw >> 12;
    int d = gw & (NN - 1);

    float gat = gat_aggregate<0>(gw, lane, b, d) + b0[lane];

    float hv = 0.f;
#pragma unroll
    for (int k = 0; k < 32; k++) {
        float gk = __shfl_sync(0xffffffffu, gat, k);
        hv += W1[lane * 32 + k] * gk;
    }
    g_hB[(size_t)gw * 32 + lane] = hv;
    float ps = hv * a1s[lane];
    float pd = hv * a1d[lane];
#pragma unroll
    for (int o = 16; o > 0; o >>= 1) {
        ps += __shfl_xor_sync(0xffffffffu, ps, o);
        pd += __shfl_xor_sync(0xffffffffu, pd, o);
    }
    if (lane == 0) { g_as1[gw] = ps; g_ad1[gw] = pd; }
}

// ============ #5: lin2 -> g_o2 (2 rows/warp for occupancy) =================
__global__ void k_lin2(const float* __restrict__ W,
                       const float* __restrict__ bias,
                       const float* __restrict__ pr,
                       const float* __restrict__ bg,
                       const float* __restrict__ bb) {
    int warp = (blockIdx.x * blockDim.x + threadIdx.x) >> 5;
    int lane = threadIdx.x & 31;
    int m0 = warp * 2;
    if (m0 >= MM2) return;
    float acc0[16], acc1[16];
#pragma unroll
    for (int b2 = 0; b2 < 16; b2++) { acc0[b2] = 0.f; acc1[b2] = 0.f; }

    const float* wr = W + (size_t)m0 * MM1;
    for (int k = lane * 4; k < MM1; k += 128) {
        float4 wv0 = __ldcs((const float4*)(wr + k));
        float4 wv1 = __ldcs((const float4*)(wr + MM1 + k));
#pragma unroll
        for (int b2 = 0; b2 < 16; b2++) {
            float4 av = *(const float4*)(g_o1 + (size_t)b2 * MM1 + k);
            acc0[b2] += wv0.x * av.x + wv0.y * av.y + wv0.z * av.z + wv0.w * av.w;
            acc1[b2] += wv1.x * av.x + wv1.y * av.y + wv1.z * av.z + wv1.w * av.w;
        }
    }
    float m0v = 0.f, m1v = 0.f;
#pragma unroll
    for (int b2 = 0; b2 < 16; b2++) {
        float v0 = acc0[b2], v1 = acc1[b2];
#pragma unroll
        for (int o = 16; o > 0; o >>= 1) {
            v0 += __shfl_xor_sync(0xffffffffu, v0, o);
            v1 += __shfl_xor_sync(0xffffffffu, v1, o);
        }
        if (lane == b2) { m0v = v0; m1v = v1; }
    }
    if (lane < 16) {
        const float inv = rsqrtf(1.f + 1e-5f);
        float t0 = m0v + bias[m0];
        t0 = t0 >= 0.f ? t0 : pr[m0] * t0;
        g_o2[(size_t)lane * MM2 + m0] = t0 * inv * bg[m0] + bb[m0];
        int m1 = m0 + 1;
        float t1 = m1v + bias[m1];
        t1 = t1 >= 0.f ? t1 : pr[m1] * t1;
        g_o2[(size_t)lane * MM2 + m1] = t1 * inv * bg[m1] + bb[m1];
    }
}

// ============ #6: agg1 + full output projection + zero-deg for next iter ===
// blocks 0..8191: agg1 (65536 warps); 8192..8207: zero g_deg.
__global__ void k_agg1_out(const float* __restrict__ b1,
                           const float* __restrict__ wo,   // [3 x 40]
                           const float* __restrict__ bo,   // [3]
                           float* __restrict__ out,
                           int nwork) {
    int blk = blockIdx.x;
    if (blk >= 8192) {
        int i = (blk - 8192) * 256 + threadIdx.x;
        if (i < NN) g_deg[i] = 0;
        return;
    }
    int gw = (blk * blockDim.x + threadIdx.x) >> 5;
    int lane = threadIdx.x & 31;
    if (gw >= nwork) return;
    int b = gw >> 12;
    int d = gw & (NN - 1);

    float gat = gat_aggregate<1>(gw, lane, b, d) + b1[lane];

    float o2v = (lane < 8) ? g_o2[(size_t)b * MM2 + d * 8 + lane] : 0.f;
    float s0 = gat * wo[8 + lane] + ((lane < 8) ? o2v * wo[lane] : 0.f);
    float s1 = gat * wo[48 + lane] + ((lane < 8) ? o2v * wo[40 + lane] : 0.f);
    float s2 = gat * wo[88 + lane] + ((lane < 8) ? o2v * wo[80 + lane] : 0.f);
#pragma unroll
    for (int o = 16; o > 0; o >>= 1) {
        s0 += __shfl_xor_sync(0xffffffffu, s0, o);
        s1 += __shfl_xor_sync(0xffffffffu, s1, o);
        s2 += __shfl_xor_sync(0xffffffffu, s2, o);
    }
    if (lane == 0) {
        size_t base = (size_t)gw * 3;
        out[base + 0] = bo[0] + s0;
        out[base + 1] = bo[1] + s1;
        out[base + 2] = bo[2] + s2;
    }
}

// ---------------- launch ----------------------------------------------------
extern "C" void kernel_launch(void* const* d_in, const int* in_sizes, int n_in,
                              void* d_out, int out_size) {
    const float* x      = (const float*)d_in[0];
    const float* svp    = (const float*)d_in[1];
    const float* hidden = (const float*)d_in[2];
    const int*   ei     = (const int*)  d_in[3];
    const float* W0     = (const float*)d_in[4];
    const float* a0s    = (const float*)d_in[5];
    const float* a0d    = (const float*)d_in[6];
    const float* b0     = (const float*)d_in[7];
    const float* W1     = (const float*)d_in[8];
    const float* a1s    = (const float*)d_in[9];
    const float* a1d    = (const float*)d_in[10];
    const float* b1     = (const float*)d_in[11];
    const float* w_ih   = (const float*)d_in[12];
    const float* w_hh   = (const float*)d_in[13];
    const float* b_ih   = (const float*)d_in[14];
    const float* b_hh   = (const float*)d_in[15];
    const float* l1w    = (const float*)d_in[16];
    const float* l1b    = (const float*)d_in[17];
    const float* pr1    = (const float*)d_in[18];
    const float* bg1    = (const float*)d_in[19];
    const float* bb1    = (const float*)d_in[20];
    const float* l2w    = (const float*)d_in[21];
    const float* l2b    = (const float*)d_in[22];
    const float* pr2    = (const float*)d_in[23];
    const float* bg2    = (const float*)d_in[24];
    const float* bb2    = (const float*)d_in[25];
    const float* wo     = (const float*)d_in[26];
    const float* bo     = (const float*)d_in[27];
    float* out = (float*)d_out;

    int write_nh = (out_size >= BB * NN * 3 + BB * HH) ? 1 : 0;

    // #1 hist + gi + gh + feat3 (g_deg zeroed by previous iteration / BSS)
    k_one<<<8832, 256>>>(ei, x, hidden, w_ih, b_ih, w_hh, b_hh, svp, W0, a0s, a0d);
    // #2 scan + combine
    k_two<<<33, 256>>>(hidden, out, write_nh);
    // #3 scatter + lin1
    k_three<<<384, 256>>>(ei, l1w, l1b, pr1, bg1, bb1);
    // #4 agg0 + layer-1 transform   <-- profiled slot
    k_agg0_feat1<<<(BB * NN) / 8, 256>>>(b0, W1, a1s, a1d, BB * NN);
    // #5 lin2 -> g_o2 (2 rows/warp)
    k_lin2<<<MM2 / 16, 256>>>(l2w, l2b, pr2, bg2, bb2);
    // #6 agg1 + output projection + zero-deg (8192 agg1 blocks + 16 zero)
    k_agg1_out<<<8192 + 16, 256>>>(b1, wo, bo, out, BB * NN);
}